// round 1
// baseline (speedup 1.0000x reference)
#include <cuda_runtime.h>
#include <cuda_bf16.h>
#include <cstdint>

#define N_NODES 100000
#define N_EDGES 1600000
#define IN_CH 128
#define HID 64
#define NUM_GRAPHS 128
#define OUT_CH 10

// ---------------- device scratch (no allocations allowed) ----------------
__device__ float g_agg[(size_t)N_NODES * IN_CH];        // 51.2 MB (reused as 64-ch for layers 1-3)
__device__ float g_hcat[(size_t)N_NODES * 4 * HID];     // 102.4 MB, layout [node][layer*64 + c]
__device__ float g_pooled[NUM_GRAPHS * HID];

// ---------------- vector red helper ----------------
__device__ __forceinline__ void red_add_v4(float* p, float4 v) {
    asm volatile("red.global.add.v4.f32 [%0], {%1,%2,%3,%4};"
                 :: "l"(p), "f"(v.x), "f"(v.y), "f"(v.z), "f"(v.w) : "memory");
}

// ---------------- scatter-add: agg[dst] += feat[src] ----------------
// QUADS = channels/4 (32 for 128ch, 16 for 64ch)
template<int QUADS>
__global__ void __launch_bounds__(256) scatter_kernel(
    const float* __restrict__ feat, int feat_stride,
    const int* __restrict__ ei,
    float* __restrict__ agg, int agg_stride)
{
    long long t = (long long)blockIdx.x * blockDim.x + threadIdx.x;
    int e = (int)(t / QUADS);
    int q = (int)(t % QUADS);
    if (e >= N_EDGES) return;
    int s = ei[e];
    int d = ei[N_EDGES + e];
    float4 v = *(const float4*)(feat + (size_t)s * feat_stride + q * 4);
    red_add_v4(agg + (size_t)d * agg_stride + q * 4, v);
}

// ---------------- fused GIN MLP: out = relu( relu((x+agg)@W1+b1) @ W2 + b2 ) ----------------
// Block: 256 threads, 128 nodes/block. Thread (n = tid&127, half = tid>>7) computes 32 out channels.
template<int K>
__global__ void __launch_bounds__(256) mlp_kernel(
    const float* __restrict__ xin, int xin_stride,
    const float* __restrict__ agg,
    const float* __restrict__ W1, const float* __restrict__ b1,
    const float* __restrict__ W2, const float* __restrict__ b2,
    float* __restrict__ out, int out_stride)
{
    extern __shared__ float sm[];
    float* zs  = sm;                       // [K][129]
    float* W1s = zs + K * 129;             // [K][64]
    float* W2s = W1s + K * 64;             // [64][64]
    float* ts  = W2s + 64 * 64;            // [64][129]

    int tid = threadIdx.x;
    int node0 = blockIdx.x * 128;

    for (int i = tid; i < K * 64; i += 256) W1s[i] = W1[i];
    for (int i = tid; i < 64 * 64; i += 256) W2s[i] = W2[i];

    // stage z = x + agg, transposed [k][n]
    for (int i = tid; i < 128 * K; i += 256) {
        int n = i / K;
        int k = i & (K - 1);
        int g = node0 + n;
        float v = 0.f;
        if (g < N_NODES)
            v = xin[(size_t)g * xin_stride + k] + agg[(size_t)g * K + k];
        zs[k * 129 + n] = v;
    }
    __syncthreads();

    int n = tid & 127;
    int half = tid >> 7;
    int cbase = half * 32;
    int g = node0 + n;

    float acc[32];
#pragma unroll
    for (int j = 0; j < 32; j++) acc[j] = b1[cbase + j];

    for (int k = 0; k < K; k += 4) {
        float zr[4];
#pragma unroll
        for (int i = 0; i < 4; i++) zr[i] = zs[(k + i) * 129 + n];
#pragma unroll
        for (int i = 0; i < 4; i++) {
#pragma unroll
            for (int j = 0; j < 32; j += 4) {
                float4 w = *(const float4*)&W1s[(k + i) * 64 + cbase + j];
                acc[j]     += zr[i] * w.x;
                acc[j + 1] += zr[i] * w.y;
                acc[j + 2] += zr[i] * w.z;
                acc[j + 3] += zr[i] * w.w;
            }
        }
    }
#pragma unroll
    for (int j = 0; j < 32; j++) ts[(cbase + j) * 129 + n] = fmaxf(acc[j], 0.f);
    __syncthreads();

#pragma unroll
    for (int j = 0; j < 32; j++) acc[j] = b2[cbase + j];

    for (int k = 0; k < 64; k += 4) {
        float zr[4];
#pragma unroll
        for (int i = 0; i < 4; i++) zr[i] = ts[(k + i) * 129 + n];
#pragma unroll
        for (int i = 0; i < 4; i++) {
#pragma unroll
            for (int j = 0; j < 32; j += 4) {
                float4 w = *(const float4*)&W2s[(k + i) * 64 + cbase + j];
                acc[j]     += zr[i] * w.x;
                acc[j + 1] += zr[i] * w.y;
                acc[j + 2] += zr[i] * w.z;
                acc[j + 3] += zr[i] * w.w;
            }
        }
    }

    if (g < N_NODES) {
        float4* o4 = (float4*)(out + (size_t)g * out_stride + cbase);
#pragma unroll
        for (int j = 0; j < 32; j += 4)
            o4[j >> 2] = make_float4(fmaxf(acc[j], 0.f), fmaxf(acc[j + 1], 0.f),
                                     fmaxf(acc[j + 2], 0.f), fmaxf(acc[j + 3], 0.f));
    }
}

// ---------------- JK projection + global add pool: pooled[batch[n]] += hcat[n]@Wjk + bjk ----------------
__global__ void __launch_bounds__(256) jk_pool_kernel(
    const float* __restrict__ hcat,
    const float* __restrict__ Wjk, const float* __restrict__ bjk,
    const int* __restrict__ batch,
    float* __restrict__ pooled)
{
    const int K = 256;
    extern __shared__ float sm[];
    float* zs = sm;              // [256][129]
    float* Ws = zs + K * 129;    // [256][64]

    int tid = threadIdx.x;
    int node0 = blockIdx.x * 128;

    for (int i = tid; i < K * 64; i += 256) Ws[i] = Wjk[i];

    for (int i = tid; i < 128 * K; i += 256) {
        int n = i / K;
        int k = i & (K - 1);
        int g = node0 + n;
        float v = 0.f;
        if (g < N_NODES) v = hcat[(size_t)g * K + k];
        zs[k * 129 + n] = v;
    }
    __syncthreads();

    int n = tid & 127;
    int half = tid >> 7;
    int cbase = half * 32;
    int g = node0 + n;

    float acc[32];
#pragma unroll
    for (int j = 0; j < 32; j++) acc[j] = bjk[cbase + j];

    for (int k = 0; k < K; k += 4) {
        float zr[4];
#pragma unroll
        for (int i = 0; i < 4; i++) zr[i] = zs[(k + i) * 129 + n];
#pragma unroll
        for (int i = 0; i < 4; i++) {
#pragma unroll
            for (int j = 0; j < 32; j += 4) {
                float4 w = *(const float4*)&Ws[(k + i) * 64 + cbase + j];
                acc[j]     += zr[i] * w.x;
                acc[j + 1] += zr[i] * w.y;
                acc[j + 2] += zr[i] * w.z;
                acc[j + 3] += zr[i] * w.w;
            }
        }
    }

    if (g < N_NODES) {
        int b = batch[g];
        float* dst = pooled + b * HID + cbase;
#pragma unroll
        for (int j = 0; j < 32; j += 4)
            red_add_v4(dst + j, make_float4(acc[j], acc[j + 1], acc[j + 2], acc[j + 3]));
    }
}

// ---------------- classifier: Linear -> BN(batch stats) -> ReLU -> Linear ----------------
__global__ void __launch_bounds__(128) classifier_kernel(
    const float* __restrict__ pooled,
    const float* __restrict__ Wc1, const float* __restrict__ bc1,
    const float* __restrict__ gamma, const float* __restrict__ beta,
    const float* __restrict__ Wc2, const float* __restrict__ bc2,
    float* __restrict__ out)
{
    extern __shared__ float sm[];
    float* W1s    = sm;                 // [64][64]
    float* zsm    = W1s + 64 * 64;      // [64][129]
    float* scale_s = zsm + 64 * 129;    // [64]
    float* shift_s = scale_s + 64;      // [64]

    int tid = threadIdx.x;  // one graph per thread
    for (int i = tid; i < 64 * 64; i += 128) W1s[i] = Wc1[i];
    __syncthreads();

    float acc[64];
#pragma unroll
    for (int c = 0; c < 64; c++) acc[c] = bc1[c];
    for (int k = 0; k < 64; k++) {
        float pk = pooled[tid * 64 + k];
#pragma unroll
        for (int c = 0; c < 64; c++) acc[c] += pk * W1s[k * 64 + c];
    }
#pragma unroll
    for (int c = 0; c < 64; c++) zsm[c * 129 + tid] = acc[c];
    __syncthreads();

    if (tid < 64) {
        int c = tid;
        float s = 0.f;
        for (int g = 0; g < NUM_GRAPHS; g++) s += zsm[c * 129 + g];
        float mu = s / NUM_GRAPHS;
        float v = 0.f;
        for (int g = 0; g < NUM_GRAPHS; g++) {
            float d = zsm[c * 129 + g] - mu;
            v += d * d;
        }
        v /= NUM_GRAPHS;
        float sc = gamma[c] * rsqrtf(v + 1e-5f);
        scale_s[c] = sc;
        shift_s[c] = beta[c] - mu * sc;
    }
    __syncthreads();

    float o[OUT_CH];
#pragma unroll
    for (int j = 0; j < OUT_CH; j++) o[j] = bc2[j];
    for (int c = 0; c < 64; c++) {
        float zn = fmaxf(zsm[c * 129 + tid] * scale_s[c] + shift_s[c], 0.f);
#pragma unroll
        for (int j = 0; j < OUT_CH; j++) o[j] += zn * Wc2[c * OUT_CH + j];
    }
#pragma unroll
    for (int j = 0; j < OUT_CH; j++) out[tid * OUT_CH + j] = o[j];
}

// ---------------- launch ----------------
extern "C" void kernel_launch(void* const* d_in, const int* in_sizes, int n_in,
                              void* d_out, int out_size)
{
    const float* x     = (const float*)d_in[0];
    const int*   ei    = (const int*)d_in[1];
    const int*   batch = (const int*)d_in[2];
    const float* W1f = (const float*)d_in[3];
    const float* b1f = (const float*)d_in[4];
    const float* W2f = (const float*)d_in[5];
    const float* b2f = (const float*)d_in[6];
    const float* W1r = (const float*)d_in[7];
    const float* b1r = (const float*)d_in[8];
    const float* W2r = (const float*)d_in[9];
    const float* b2r = (const float*)d_in[10];
    const float* Wjk = (const float*)d_in[11];
    const float* bjk = (const float*)d_in[12];
    const float* Wc1 = (const float*)d_in[13];
    const float* bc1 = (const float*)d_in[14];
    const float* gm  = (const float*)d_in[15];
    const float* bt  = (const float*)d_in[16];
    const float* Wc2 = (const float*)d_in[17];
    const float* bc2 = (const float*)d_in[18];
    float* out = (float*)d_out;

    void *p_agg, *p_hcat, *p_pooled;
    cudaGetSymbolAddress(&p_agg, g_agg);
    cudaGetSymbolAddress(&p_hcat, g_hcat);
    cudaGetSymbolAddress(&p_pooled, g_pooled);
    float* agg    = (float*)p_agg;
    float* hcat   = (float*)p_hcat;
    float* pooled = (float*)p_pooled;

    const size_t SM_MLP128 = (128 * 129 + 128 * 64 + 64 * 64 + 64 * 129) * sizeof(float); // 148224
    const size_t SM_MLP64  = (64 * 129 + 64 * 64 + 64 * 64 + 64 * 129) * sizeof(float);   // 98816
    const size_t SM_JK     = (256 * 129 + 256 * 64) * sizeof(float);                      // 197632
    const size_t SM_CLS    = (64 * 64 + 64 * 129 + 128) * sizeof(float);                  // 49920

    cudaFuncSetAttribute(mlp_kernel<128>, cudaFuncAttributeMaxDynamicSharedMemorySize, (int)SM_MLP128);
    cudaFuncSetAttribute(mlp_kernel<64>,  cudaFuncAttributeMaxDynamicSharedMemorySize, (int)SM_MLP64);
    cudaFuncSetAttribute(jk_pool_kernel,  cudaFuncAttributeMaxDynamicSharedMemorySize, (int)SM_JK);
    cudaFuncSetAttribute(classifier_kernel, cudaFuncAttributeMaxDynamicSharedMemorySize, (int)SM_CLS);

    const int NODE_BLOCKS = (N_NODES + 127) / 128;  // 782

    // ---- layer 0 (K = 128) ----
    cudaMemsetAsync(agg, 0, (size_t)N_NODES * IN_CH * sizeof(float), 0);
    {
        long long tot = (long long)N_EDGES * 32;
        int blocks = (int)((tot + 255) / 256);
        scatter_kernel<32><<<blocks, 256>>>(x, IN_CH, ei, agg, IN_CH);
    }
    mlp_kernel<128><<<NODE_BLOCKS, 256, SM_MLP128>>>(
        x, IN_CH, agg, W1f, b1f, W2f, b2f, hcat + 0, 4 * HID);

    // ---- layers 1..3 (K = 64) ----
    for (int l = 1; l < 4; l++) {
        cudaMemsetAsync(agg, 0, (size_t)N_NODES * HID * sizeof(float), 0);
        long long tot = (long long)N_EDGES * 16;
        int blocks = (int)((tot + 255) / 256);
        scatter_kernel<16><<<blocks, 256>>>(hcat + (l - 1) * HID, 4 * HID, ei, agg, HID);
        mlp_kernel<64><<<NODE_BLOCKS, 256, SM_MLP64>>>(
            hcat + (l - 1) * HID, 4 * HID, agg,
            W1r + (size_t)(l - 1) * HID * HID, b1r + (size_t)(l - 1) * HID,
            W2r + (size_t)(l - 1) * HID * HID, b2r + (size_t)(l - 1) * HID,
            hcat + l * HID, 4 * HID);
    }

    // ---- JK projection + pooling ----
    cudaMemsetAsync(pooled, 0, NUM_GRAPHS * HID * sizeof(float), 0);
    jk_pool_kernel<<<NODE_BLOCKS, 256, SM_JK>>>(hcat, Wjk, bjk, batch, pooled);

    // ---- classifier ----
    classifier_kernel<<<1, 128, SM_CLS>>>(pooled, Wc1, bc1, gm, bt, Wc2, bc2, out);
}

// round 2
// speedup vs baseline: 2.0520x; 2.0520x over previous
#include <cuda_runtime.h>
#include <cuda_bf16.h>
#include <cstdint>

#define NN 100000
#define NE 1600000
#define GNUM 128
#define OUT_CH 10

// ---------------- device scratch ----------------
__device__ int   g_deg[NN];
__device__ int   g_rowptr[NN + 1];
__device__ int   g_cursor[NN];
__device__ int   g_esrc[NE];
__device__ int   g_bsum[128];
__device__ float g_y[(size_t)NN * 64];
__device__ float g_t[(size_t)NN * 64];
__device__ float g_hcat[(size_t)4 * NN * 64];   // 4 planes [layer][node][64]
__device__ float g_pcat[GNUM * 256];            // k = layer*64 + c
__device__ int   g_cnt[GNUM];
__device__ float g_pooled[GNUM * 64];

__device__ __forceinline__ void red_add_v4(float* p, float4 v) {
    asm volatile("red.global.add.v4.f32 [%0], {%1,%2,%3,%4};"
                 :: "l"(p), "f"(v.x), "f"(v.y), "f"(v.z), "f"(v.w) : "memory");
}

// ---------------- CSR build ----------------
__global__ void hist_kernel(const int* __restrict__ ei) {
    int e = blockIdx.x * blockDim.x + threadIdx.x;
    if (e < NE) atomicAdd(&g_deg[ei[NE + e]], 1);
}

__global__ void scan1_kernel() {
    __shared__ int wsum[8];
    int tid = threadIdx.x;
    int base = blockIdx.x * 1024 + tid * 4;
    int v[4];
#pragma unroll
    for (int i = 0; i < 4; i++) v[i] = (base + i < NN) ? g_deg[base + i] : 0;
    int s = v[0] + v[1] + v[2] + v[3];
    int lane = tid & 31, w = tid >> 5;
    int inc = s;
    for (int o = 1; o < 32; o <<= 1) {
        int t = __shfl_up_sync(0xffffffffu, inc, o);
        if (lane >= o) inc += t;
    }
    if (lane == 31) wsum[w] = inc;
    __syncthreads();
    if (tid < 8) {
        int x = wsum[tid];
        int inc2 = x;
        for (int o = 1; o < 8; o <<= 1) {
            int t = __shfl_up_sync(0xffu, inc2, o);
            if (tid >= o) inc2 += t;
        }
        wsum[tid] = inc2 - x;  // exclusive warp base
        if (tid == 7) g_bsum[blockIdx.x] = inc2;  // block total
    }
    __syncthreads();
    int run = wsum[w] + inc - s;  // thread-exclusive prefix
#pragma unroll
    for (int i = 0; i < 4; i++) {
        if (base + i < NN) g_deg[base + i] = run;
        run += v[i];
    }
}

__global__ void scan2_kernel(int nb) {
    __shared__ int ws[4];
    int tid = threadIdx.x;
    int v = (tid < nb) ? g_bsum[tid] : 0;
    int lane = tid & 31, w = tid >> 5;
    int inc = v;
    for (int o = 1; o < 32; o <<= 1) {
        int t = __shfl_up_sync(0xffffffffu, inc, o);
        if (lane >= o) inc += t;
    }
    if (lane == 31) ws[w] = inc;
    __syncthreads();
    int add = 0;
    for (int i = 0; i < w; i++) add += ws[i];
    if (tid < nb) g_bsum[tid] = add + inc - v;  // exclusive
}

__global__ void scan3_kernel() {
    int tid = threadIdx.x;
    int base = blockIdx.x * 1024 + tid * 4;
    int add = g_bsum[blockIdx.x];
#pragma unroll
    for (int i = 0; i < 4; i++) {
        int idx = base + i;
        if (idx < NN) {
            int r = g_deg[idx] + add;
            g_rowptr[idx] = r;
            g_cursor[idx] = r;
        }
    }
    if (blockIdx.x == 0 && tid == 0) g_rowptr[NN] = NE;
}

__global__ void fill_kernel(const int* __restrict__ ei) {
    int e = blockIdx.x * blockDim.x + threadIdx.x;
    if (e < NE) {
        int d = ei[NE + e];
        int p = atomicAdd(&g_cursor[d], 1);
        g_esrc[p] = ei[e];
    }
}

// ---------------- y0 = x @ W1f (K=128 -> 64) ----------------
__global__ void __launch_bounds__(256) gemm_y0_kernel(
    const float* __restrict__ x, const float* __restrict__ W)
{
    extern __shared__ float sm[];
    float* zs = sm;            // [128][65]
    float* ws = zs + 128 * 65; // [128][64]
    int tid = threadIdx.x;
    int node0 = blockIdx.x * 64;

    for (int i = tid; i < 128 * 64; i += 256) ws[i] = W[i];
    for (int i = tid; i < 2048; i += 256) {     // 64 nodes x 32 float4
        int n = i >> 5, kq = i & 31;
        int gn = node0 + n;
        float4 v = (gn < NN) ? *(const float4*)(x + (size_t)gn * 128 + kq * 4)
                             : make_float4(0.f, 0.f, 0.f, 0.f);
        zs[(4 * kq + 0) * 65 + n] = v.x;
        zs[(4 * kq + 1) * 65 + n] = v.y;
        zs[(4 * kq + 2) * 65 + n] = v.z;
        zs[(4 * kq + 3) * 65 + n] = v.w;
    }
    __syncthreads();

    int n = tid & 63, grp = tid >> 6, cb = grp * 16;
    float acc[16];
#pragma unroll
    for (int j = 0; j < 16; j++) acc[j] = 0.f;
    for (int k = 0; k < 128; k++) {
        float z = zs[k * 65 + n];
#pragma unroll
        for (int j = 0; j < 16; j += 4) {
            float4 w = *(const float4*)&ws[k * 64 + cb + j];
            acc[j]     += z * w.x;
            acc[j + 1] += z * w.y;
            acc[j + 2] += z * w.z;
            acc[j + 3] += z * w.w;
        }
    }
    int gn = node0 + n;
    if (gn < NN) {
        float4* o = (float4*)(g_y + (size_t)gn * 64 + cb);
#pragma unroll
        for (int j = 0; j < 16; j += 4)
            o[j >> 2] = make_float4(acc[j], acc[j + 1], acc[j + 2], acc[j + 3]);
    }
}

// ---------------- gather: t[n] = relu(y[n] + sum_in y[src] + b1) ----------------
__global__ void __launch_bounds__(256) gather_kernel(
    const float* __restrict__ y, const float* __restrict__ b1,
    float* __restrict__ tout)
{
    int tid = threadIdx.x;
    int n = blockIdx.x * 16 + (tid >> 4);
    int q = tid & 15;
    if (n >= NN) return;
    int beg = g_rowptr[n], end = g_rowptr[n + 1];
    const float4* yb = (const float4*)y;
    float4 a = yb[(size_t)n * 16 + q];
    float4 bb = *(const float4*)(b1 + q * 4);
    a.x += bb.x; a.y += bb.y; a.z += bb.z; a.w += bb.w;
    for (int e = beg; e < end; e++) {
        int s = g_esrc[e];
        float4 v = yb[(size_t)s * 16 + q];
        a.x += v.x; a.y += v.y; a.z += v.z; a.w += v.w;
    }
    *(float4*)(tout + (size_t)n * 64 + q * 4) =
        make_float4(fmaxf(a.x, 0.f), fmaxf(a.y, 0.f), fmaxf(a.z, 0.f), fmaxf(a.w, 0.f));
}

// ---------------- fused: h = relu(t@W2+b2) -> hout;  y = h@W1n (if SECOND) ----------------
template<bool SECOND>
__global__ void __launch_bounds__(256) mlp2_kernel(
    const float* __restrict__ tin,
    const float* __restrict__ W2, const float* __restrict__ b2,
    float* __restrict__ hout,
    const float* __restrict__ W1n, float* __restrict__ yout)
{
    extern __shared__ float sm[];
    float* zs = sm;              // [64][65]
    float* w2 = zs + 64 * 65;    // [64][64]
    float* hs = w2 + 4096;       // [64][65]
    float* w1 = hs + 64 * 65;    // [64][64]
    int tid = threadIdx.x;
    int node0 = blockIdx.x * 64;

    for (int i = tid; i < 4096; i += 256) {
        w2[i] = W2[i];
        if (SECOND) w1[i] = W1n[i];
    }
    for (int i = tid; i < 1024; i += 256) {    // 64 nodes x 16 float4
        int n = i >> 4, kq = i & 15;
        int gn = node0 + n;
        float4 v = (gn < NN) ? *(const float4*)(tin + (size_t)gn * 64 + kq * 4)
                             : make_float4(0.f, 0.f, 0.f, 0.f);
        zs[(4 * kq + 0) * 65 + n] = v.x;
        zs[(4 * kq + 1) * 65 + n] = v.y;
        zs[(4 * kq + 2) * 65 + n] = v.z;
        zs[(4 * kq + 3) * 65 + n] = v.w;
    }
    __syncthreads();

    int n = tid & 63, grp = tid >> 6, cb = grp * 16;
    int gn = node0 + n;
    float acc[16];
#pragma unroll
    for (int j = 0; j < 16; j++) acc[j] = b2[cb + j];
    for (int k = 0; k < 64; k++) {
        float z = zs[k * 65 + n];
#pragma unroll
        for (int j = 0; j < 16; j += 4) {
            float4 w = *(const float4*)&w2[k * 64 + cb + j];
            acc[j]     += z * w.x;
            acc[j + 1] += z * w.y;
            acc[j + 2] += z * w.z;
            acc[j + 3] += z * w.w;
        }
    }
#pragma unroll
    for (int j = 0; j < 16; j++) {
        float h = fmaxf(acc[j], 0.f);
        acc[j] = h;
        if (SECOND) hs[(cb + j) * 65 + n] = h;
    }
    if (gn < NN) {
        float4* o = (float4*)(hout + (size_t)gn * 64 + cb);
#pragma unroll
        for (int j = 0; j < 16; j += 4)
            o[j >> 2] = make_float4(acc[j], acc[j + 1], acc[j + 2], acc[j + 3]);
    }
    if (!SECOND) return;
    __syncthreads();

    float a2[16];
#pragma unroll
    for (int j = 0; j < 16; j++) a2[j] = 0.f;
    for (int k = 0; k < 64; k++) {
        float z = hs[k * 65 + n];
#pragma unroll
        for (int j = 0; j < 16; j += 4) {
            float4 w = *(const float4*)&w1[k * 64 + cb + j];
            a2[j]     += z * w.x;
            a2[j + 1] += z * w.y;
            a2[j + 2] += z * w.z;
            a2[j + 3] += z * w.w;
        }
    }
    if (gn < NN) {
        float4* o = (float4*)(yout + (size_t)gn * 64 + cb);
#pragma unroll
        for (int j = 0; j < 16; j += 4)
            o[j >> 2] = make_float4(a2[j], a2[j + 1], a2[j + 2], a2[j + 3]);
    }
}

// ---------------- graph counts ----------------
__global__ void cnt_kernel(const int* __restrict__ batch) {
    __shared__ int h[GNUM];
    int tid = threadIdx.x;
    if (tid < GNUM) h[tid] = 0;
    __syncthreads();
    int i = blockIdx.x * 256 + tid;
    if (i < NN) atomicAdd(&h[batch[i]], 1);
    __syncthreads();
    if (tid < GNUM && h[tid]) atomicAdd(&g_cnt[tid], h[tid]);
}

// ---------------- pool: pcat[g][k] = sum_n hcat ----------------
__global__ void __launch_bounds__(64) pool_kernel(const int* __restrict__ batch) {
    int q = threadIdx.x;            // 0..63 quads over k=0..255 (layer-major)
    int l = q >> 4;
    int qq = q & 15;
    int node0 = blockIdx.x * 64;
    int nmax = min(64, NN - node0);
    const float4* hb = (const float4*)(g_hcat + (size_t)l * NN * 64);
    float4 a = make_float4(0.f, 0.f, 0.f, 0.f);
    int cur = batch[node0];
    for (int i = 0; i < nmax; i++) {
        int b = batch[node0 + i];
        if (b != cur) {
            red_add_v4(&g_pcat[cur * 256 + q * 4], a);
            a = make_float4(0.f, 0.f, 0.f, 0.f);
            cur = b;
        }
        float4 v = hb[((size_t)(node0 + i)) * 16 + qq];
        a.x += v.x; a.y += v.y; a.z += v.z; a.w += v.w;
    }
    red_add_v4(&g_pcat[cur * 256 + q * 4], a);
}

// ---------------- JK projection on pooled: pooled[g] = pcat[g]@Wjk + cnt*bjk ----------------
__global__ void __launch_bounds__(64) proj_kernel(
    const float* __restrict__ Wjk, const float* __restrict__ bjk)
{
    __shared__ float ps[256];
    int g = blockIdx.x, c = threadIdx.x;
    for (int i = c; i < 256; i += 64) ps[i] = g_pcat[g * 256 + i];
    __syncthreads();
    float acc = (float)g_cnt[g] * bjk[c];
    for (int k = 0; k < 256; k++) acc += ps[k] * Wjk[k * 64 + c];
    g_pooled[g * 64 + c] = acc;
}

// ---------------- classifier ----------------
__global__ void __launch_bounds__(128) classifier_kernel(
    const float* __restrict__ Wc1, const float* __restrict__ bc1,
    const float* __restrict__ gamma, const float* __restrict__ beta,
    const float* __restrict__ Wc2, const float* __restrict__ bc2,
    float* __restrict__ out)
{
    extern __shared__ float sm[];
    float* W1s = sm;                  // [64][64]
    float* zsm = W1s + 64 * 64;       // [64][129]
    float* scale_s = zsm + 64 * 129;
    float* shift_s = scale_s + 64;

    int tid = threadIdx.x;
    for (int i = tid; i < 64 * 64; i += 128) W1s[i] = Wc1[i];
    __syncthreads();

    float acc[64];
#pragma unroll
    for (int c = 0; c < 64; c++) acc[c] = bc1[c];
    for (int k = 0; k < 64; k++) {
        float pk = g_pooled[tid * 64 + k];
#pragma unroll
        for (int c = 0; c < 64; c++) acc[c] += pk * W1s[k * 64 + c];
    }
#pragma unroll
    for (int c = 0; c < 64; c++) zsm[c * 129 + tid] = acc[c];
    __syncthreads();

    if (tid < 64) {
        int c = tid;
        float s = 0.f;
        for (int g = 0; g < GNUM; g++) s += zsm[c * 129 + g];
        float mu = s / GNUM;
        float v = 0.f;
        for (int g = 0; g < GNUM; g++) {
            float d = zsm[c * 129 + g] - mu;
            v += d * d;
        }
        v /= GNUM;
        float sc = gamma[c] * rsqrtf(v + 1e-5f);
        scale_s[c] = sc;
        shift_s[c] = beta[c] - mu * sc;
    }
    __syncthreads();

    float o[OUT_CH];
#pragma unroll
    for (int j = 0; j < OUT_CH; j++) o[j] = bc2[j];
    for (int c = 0; c < 64; c++) {
        float zn = fmaxf(zsm[c * 129 + tid] * scale_s[c] + shift_s[c], 0.f);
#pragma unroll
        for (int j = 0; j < OUT_CH; j++) o[j] += zn * Wc2[c * OUT_CH + j];
    }
#pragma unroll
    for (int j = 0; j < OUT_CH; j++) out[tid * OUT_CH + j] = o[j];
}

// ---------------- launch ----------------
extern "C" void kernel_launch(void* const* d_in, const int* in_sizes, int n_in,
                              void* d_out, int out_size)
{
    const float* x     = (const float*)d_in[0];
    const int*   ei    = (const int*)d_in[1];
    const int*   batch = (const int*)d_in[2];
    const float* W1f = (const float*)d_in[3];
    const float* b1f = (const float*)d_in[4];
    const float* W2f = (const float*)d_in[5];
    const float* b2f = (const float*)d_in[6];
    const float* W1r = (const float*)d_in[7];
    const float* b1r = (const float*)d_in[8];
    const float* W2r = (const float*)d_in[9];
    const float* b2r = (const float*)d_in[10];
    const float* Wjk = (const float*)d_in[11];
    const float* bjk = (const float*)d_in[12];
    const float* Wc1 = (const float*)d_in[13];
    const float* bc1 = (const float*)d_in[14];
    const float* gm  = (const float*)d_in[15];
    const float* bt  = (const float*)d_in[16];
    const float* Wc2 = (const float*)d_in[17];
    const float* bc2 = (const float*)d_in[18];
    float* out = (float*)d_out;

    void *p_deg, *p_pcat, *p_cnt, *p_y, *p_t, *p_hcat;
    cudaGetSymbolAddress(&p_deg, g_deg);
    cudaGetSymbolAddress(&p_pcat, g_pcat);
    cudaGetSymbolAddress(&p_cnt, g_cnt);
    cudaGetSymbolAddress(&p_y, g_y);
    cudaGetSymbolAddress(&p_t, g_t);
    cudaGetSymbolAddress(&p_hcat, g_hcat);
    float* y = (float*)p_y;
    float* t = (float*)p_t;
    float* hcat = (float*)p_hcat;

    const size_t SM_Y0  = (128 * 65 + 128 * 64) * sizeof(float);            // 66048
    const size_t SM_MLP = (64 * 65 * 2 + 4096 * 2) * sizeof(float);         // 66048
    const size_t SM_CLS = (64 * 64 + 64 * 129 + 128) * sizeof(float);       // 49920

    cudaFuncSetAttribute(gemm_y0_kernel, cudaFuncAttributeMaxDynamicSharedMemorySize, (int)SM_Y0);
    cudaFuncSetAttribute(mlp2_kernel<true>,  cudaFuncAttributeMaxDynamicSharedMemorySize, (int)SM_MLP);
    cudaFuncSetAttribute(mlp2_kernel<false>, cudaFuncAttributeMaxDynamicSharedMemorySize, (int)SM_MLP);
    cudaFuncSetAttribute(classifier_kernel, cudaFuncAttributeMaxDynamicSharedMemorySize, (int)SM_CLS);

    const int EB = (NE + 255) / 256;       // 6250
    const int SB = (NN + 1023) / 1024;     // 98
    const int GB64 = (NN + 63) / 64;       // 1563

    // CSR build
    cudaMemsetAsync(p_deg, 0, NN * sizeof(int), 0);
    cudaMemsetAsync(p_pcat, 0, GNUM * 256 * sizeof(float), 0);
    cudaMemsetAsync(p_cnt, 0, GNUM * sizeof(int), 0);
    hist_kernel<<<EB, 256>>>(ei);
    scan1_kernel<<<SB, 256>>>();
    scan2_kernel<<<1, 128>>>(SB);
    scan3_kernel<<<SB, 256>>>();
    fill_kernel<<<EB, 256>>>(ei);

    // y0 = x @ W1f
    gemm_y0_kernel<<<GB64, 256, SM_Y0>>>(x, W1f);

    // layers
    for (int l = 0; l < 4; l++) {
        const float* b1 = (l == 0) ? b1f : b1r + (size_t)(l - 1) * 64;
        const float* W2 = (l == 0) ? W2f : W2r + (size_t)(l - 1) * 4096;
        const float* b2 = (l == 0) ? b2f : b2r + (size_t)(l - 1) * 64;
        gather_kernel<<<EB, 256>>>(y, b1, t);
        float* hout = hcat + (size_t)l * NN * 64;
        if (l < 3) {
            const float* W1n = W1r + (size_t)l * 4096;
            mlp2_kernel<true><<<GB64, 256, SM_MLP>>>(t, W2, b2, hout, W1n, y);
        } else {
            mlp2_kernel<false><<<GB64, 256, SM_MLP>>>(t, W2, b2, hout, nullptr, nullptr);
        }
    }

    // pool + JK projection + classifier
    cnt_kernel<<<(NN + 255) / 256, 256>>>(batch);
    pool_kernel<<<GB64, 64>>>(batch);
    proj_kernel<<<GNUM, 64>>>(Wjk, bjk);
    classifier_kernel<<<1, 128, SM_CLS>>>(Wc1, bc1, gm, bt, Wc2, bc2, out);
}

// round 4
// speedup vs baseline: 2.2449x; 1.0940x over previous
#include <cuda_runtime.h>
#include <cstdint>

#define NN 100000
#define NE 1600000
#define GNUM 128
#define OUT_CH 10

typedef unsigned long long u64;

// ---------------- device scratch ----------------
__device__ int   g_deg[NN];
__device__ int   g_rowptr[NN + 1];
__device__ int   g_cursor[NN];
__device__ int   g_esrc[NE];
__device__ int   g_bsum[128];
__device__ float g_y[(size_t)NN * 64];
__device__ float g_t[(size_t)NN * 64];
__device__ float g_pcat[GNUM * 256];            // k = layer*64 + c
__device__ int   g_cnt[GNUM];
__device__ float g_pooled[GNUM * 64];

// ---------------- f32x2 helpers ----------------
__device__ __forceinline__ u64 pack2(float lo, float hi) {
    u64 r; asm("mov.b64 %0, {%1, %2};" : "=l"(r) : "f"(lo), "f"(hi)); return r;
}
__device__ __forceinline__ u64 dup2(float v) {
    u64 r; asm("mov.b64 %0, {%1, %1};" : "=l"(r) : "f"(v)); return r;
}
__device__ __forceinline__ void fma2(u64& d, u64 a, u64 b) {
    asm("fma.rn.f32x2 %0, %1, %2, %0;" : "+l"(d) : "l"(a), "l"(b));
}
__device__ __forceinline__ float2 unpack2(u64 v) {
    float2 f; asm("mov.b64 {%0, %1}, %2;" : "=f"(f.x), "=f"(f.y) : "l"(v)); return f;
}
__device__ __forceinline__ void red_f32(float* p, float v) {
    asm volatile("red.global.add.f32 [%0], %1;" :: "l"(p), "f"(v) : "memory");
}

// ---------------- CSR build ----------------
__global__ void hist_kernel(const int* __restrict__ ei) {
    int e = blockIdx.x * blockDim.x + threadIdx.x;
    if (e < NE) atomicAdd(&g_deg[ei[NE + e]], 1);
}

__global__ void scan1_kernel() {
    __shared__ int wsum[8];
    int tid = threadIdx.x;
    int base = blockIdx.x * 1024 + tid * 4;
    int v[4];
#pragma unroll
    for (int i = 0; i < 4; i++) v[i] = (base + i < NN) ? g_deg[base + i] : 0;
    int s = v[0] + v[1] + v[2] + v[3];
    int lane = tid & 31, w = tid >> 5;
    int inc = s;
    for (int o = 1; o < 32; o <<= 1) {
        int t = __shfl_up_sync(0xffffffffu, inc, o);
        if (lane >= o) inc += t;
    }
    if (lane == 31) wsum[w] = inc;
    __syncthreads();
    if (tid < 8) {
        int x = wsum[tid];
        int inc2 = x;
        for (int o = 1; o < 8; o <<= 1) {
            int t = __shfl_up_sync(0xffu, inc2, o);
            if (tid >= o) inc2 += t;
        }
        wsum[tid] = inc2 - x;
        if (tid == 7) g_bsum[blockIdx.x] = inc2;
    }
    __syncthreads();
    int run = wsum[w] + inc - s;
#pragma unroll
    for (int i = 0; i < 4; i++) {
        if (base + i < NN) g_deg[base + i] = run;
        run += v[i];
    }
}

__global__ void scan2_kernel(int nb) {
    __shared__ int ws[4];
    int tid = threadIdx.x;
    int v = (tid < nb) ? g_bsum[tid] : 0;
    int lane = tid & 31, w = tid >> 5;
    int inc = v;
    for (int o = 1; o < 32; o <<= 1) {
        int t = __shfl_up_sync(0xffffffffu, inc, o);
        if (lane >= o) inc += t;
    }
    if (lane == 31) ws[w] = inc;
    __syncthreads();
    int add = 0;
    for (int i = 0; i < w; i++) add += ws[i];
    if (tid < nb) g_bsum[tid] = add + inc - v;
}

__global__ void scan3_kernel() {
    int tid = threadIdx.x;
    int base = blockIdx.x * 1024 + tid * 4;
    int add = g_bsum[blockIdx.x];
#pragma unroll
    for (int i = 0; i < 4; i++) {
        int idx = base + i;
        if (idx < NN) {
            int r = g_deg[idx] + add;
            g_rowptr[idx] = r;
            g_cursor[idx] = r;
        }
    }
    if (blockIdx.x == 0 && tid == 0) g_rowptr[NN] = NE;
}

__global__ void fill_kernel(const int* __restrict__ ei) {
    int e = blockIdx.x * blockDim.x + threadIdx.x;
    if (e < NE) {
        int d = ei[NE + e];
        int p = atomicAdd(&g_cursor[d], 1);
        g_esrc[p] = ei[e];
    }
}

// ---------------- y0 = x @ W1f (K=128 -> 64), f32x2 ----------------
__global__ void __launch_bounds__(256) gemm_y0_kernel(
    const float* __restrict__ x, const float* __restrict__ W)
{
    extern __shared__ float sm[];
    float* zs = sm;            // [128][65]
    float* ws = zs + 128 * 65; // [128][64]
    int tid = threadIdx.x;
    int node0 = blockIdx.x * 64;

    for (int i = tid; i < 128 * 64; i += 256) ws[i] = W[i];
    for (int i = tid; i < 2048; i += 256) {     // 64 nodes x 32 float4
        int n = i >> 5, kq = i & 31;
        int gn = node0 + n;
        float4 v = (gn < NN) ? *(const float4*)(x + (size_t)gn * 128 + kq * 4)
                             : make_float4(0.f, 0.f, 0.f, 0.f);
        zs[(4 * kq + 0) * 65 + n] = v.x;
        zs[(4 * kq + 1) * 65 + n] = v.y;
        zs[(4 * kq + 2) * 65 + n] = v.z;
        zs[(4 * kq + 3) * 65 + n] = v.w;
    }
    __syncthreads();

    int n = tid & 63, grp = tid >> 6, cb = grp * 16;
    u64 acc[8];
#pragma unroll
    for (int j = 0; j < 8; j++) acc[j] = 0ull;
    for (int k = 0; k < 128; k++) {
        u64 zz = dup2(zs[k * 65 + n]);
        const ulonglong2* wr = (const ulonglong2*)&ws[k * 64 + cb];
#pragma unroll
        for (int j = 0; j < 4; j++) {
            ulonglong2 w = wr[j];
            fma2(acc[2 * j], zz, w.x);
            fma2(acc[2 * j + 1], zz, w.y);
        }
    }
    int gn = node0 + n;
    if (gn < NN) {
        float4* o = (float4*)(g_y + (size_t)gn * 64 + cb);
#pragma unroll
        for (int j = 0; j < 4; j++) {
            float2 a = unpack2(acc[2 * j]);
            float2 b = unpack2(acc[2 * j + 1]);
            o[j] = make_float4(a.x, a.y, b.x, b.y);
        }
    }
}

// ---------------- gather: t[n] = relu(y[n] + sum_in y[src] + b1) ----------------
__global__ void __launch_bounds__(256) gather_kernel(
    const float* __restrict__ y, const float* __restrict__ b1,
    float* __restrict__ tout)
{
    int tid = threadIdx.x;
    int n = blockIdx.x * 16 + (tid >> 4);
    int q = tid & 15;
    if (n >= NN) return;
    int beg = g_rowptr[n], end = g_rowptr[n + 1];
    const float4* yb = (const float4*)y;
    float4 a = yb[(size_t)n * 16 + q];
    float4 bb = *(const float4*)(b1 + q * 4);
    a.x += bb.x; a.y += bb.y; a.z += bb.z; a.w += bb.w;
    for (int e = beg; e < end; e++) {
        int s = g_esrc[e];
        float4 v = yb[(size_t)s * 16 + q];
        a.x += v.x; a.y += v.y; a.z += v.z; a.w += v.w;
    }
    *(float4*)(tout + (size_t)n * 64 + q * 4) =
        make_float4(fmaxf(a.x, 0.f), fmaxf(a.y, 0.f), fmaxf(a.z, 0.f), fmaxf(a.w, 0.f));
}

// -------- fused: h = relu(t@W2+b2); pool h per-graph into pcat; y = h@W1n (if SECOND) --------
template<bool SECOND>
__global__ void __launch_bounds__(256) mlp2_kernel(
    const float* __restrict__ tin,
    const float* __restrict__ W2, const float* __restrict__ b2,
    const int* __restrict__ batch, int layer,
    const float* __restrict__ W1n, float* __restrict__ yout)
{
    extern __shared__ float sm[];
    float* zs = sm;              // [64][65]
    float* w2 = zs + 64 * 65;    // [64][64]
    float* hs = w2 + 4096;       // [64][65]  (h transposed [c][n])
    float* w1 = hs + 64 * 65;    // [64][64]
    int*   sb = (int*)(w1 + 4096); // [64] batch ids
    int tid = threadIdx.x;
    int node0 = blockIdx.x * 64;
    int nmax = min(64, NN - node0);

    for (int i = tid; i < 4096; i += 256) {
        w2[i] = W2[i];
        if (SECOND) w1[i] = W1n[i];
    }
    if (tid < 64) sb[tid] = (tid < nmax) ? batch[node0 + tid] : -1;
    for (int i = tid; i < 1024; i += 256) {    // 64 nodes x 16 float4
        int n = i >> 4, kq = i & 15;
        int gn = node0 + n;
        float4 v = (gn < NN) ? *(const float4*)(tin + (size_t)gn * 64 + kq * 4)
                             : make_float4(0.f, 0.f, 0.f, 0.f);
        zs[(4 * kq + 0) * 65 + n] = v.x;
        zs[(4 * kq + 1) * 65 + n] = v.y;
        zs[(4 * kq + 2) * 65 + n] = v.z;
        zs[(4 * kq + 3) * 65 + n] = v.w;
    }
    __syncthreads();

    int n = tid & 63, grp = tid >> 6, cb = grp * 16;
    int gn = node0 + n;

    // ---- GEMM 1: h = relu(t @ W2 + b2) ----
    u64 acc[8];
#pragma unroll
    for (int j = 0; j < 8; j++) acc[j] = pack2(b2[cb + 2 * j], b2[cb + 2 * j + 1]);
    for (int k = 0; k < 64; k++) {
        u64 zz = dup2(zs[k * 65 + n]);
        const ulonglong2* wr = (const ulonglong2*)&w2[k * 64 + cb];
#pragma unroll
        for (int j = 0; j < 4; j++) {
            ulonglong2 w = wr[j];
            fma2(acc[2 * j], zz, w.x);
            fma2(acc[2 * j + 1], zz, w.y);
        }
    }
#pragma unroll
    for (int j = 0; j < 8; j++) {
        float2 a = unpack2(acc[j]);
        hs[(cb + 2 * j) * 65 + n]     = fmaxf(a.x, 0.f);
        hs[(cb + 2 * j + 1) * 65 + n] = fmaxf(a.y, 0.f);
    }
    __syncthreads();

    // ---- pooling: per-graph partial sums of h into pcat (batch is sorted) ----
    {
        int c = tid & 63;          // channel
        int q = tid >> 6;          // node chunk q*16 .. q*16+15
        int i0 = q * 16;
        if (i0 < nmax) {
            int iend = min(i0 + 16, nmax);
            int cur = sb[i0];
            float s = 0.f;
            for (int i = i0; i < iend; i++) {
                int b = sb[i];
                if (b != cur) {
                    red_f32(&g_pcat[cur * 256 + layer * 64 + c], s);
                    s = 0.f;
                    cur = b;
                }
                s += hs[c * 65 + i];
            }
            red_f32(&g_pcat[cur * 256 + layer * 64 + c], s);
        }
    }

    // ---- GEMM 2: y = h @ W1_next ----
    if (!SECOND) return;
    u64 a2[8];
#pragma unroll
    for (int j = 0; j < 8; j++) a2[j] = 0ull;
    for (int k = 0; k < 64; k++) {
        u64 zz = dup2(hs[k * 65 + n]);
        const ulonglong2* wr = (const ulonglong2*)&w1[k * 64 + cb];
#pragma unroll
        for (int j = 0; j < 4; j++) {
            ulonglong2 w = wr[j];
            fma2(a2[2 * j], zz, w.x);
            fma2(a2[2 * j + 1], zz, w.y);
        }
    }
    if (gn < NN) {
        float4* o = (float4*)(yout + (size_t)gn * 64 + cb);
#pragma unroll
        for (int j = 0; j < 4; j++) {
            float2 a = unpack2(a2[2 * j]);
            float2 b = unpack2(a2[2 * j + 1]);
            o[j] = make_float4(a.x, a.y, b.x, b.y);
        }
    }
}

// ---------------- graph counts ----------------
__global__ void cnt_kernel(const int* __restrict__ batch) {
    __shared__ int h[GNUM];
    int tid = threadIdx.x;
    if (tid < GNUM) h[tid] = 0;
    __syncthreads();
    int i = blockIdx.x * 256 + tid;
    if (i < NN) atomicAdd(&h[batch[i]], 1);
    __syncthreads();
    if (tid < GNUM && h[tid]) atomicAdd(&g_cnt[tid], h[tid]);
}

// ---------------- JK projection on pooled ----------------
__global__ void __launch_bounds__(64) proj_kernel(
    const float* __restrict__ Wjk, const float* __restrict__ bjk)
{
    __shared__ float ps[256];
    int g = blockIdx.x, c = threadIdx.x;
    for (int i = c; i < 256; i += 64) ps[i] = g_pcat[g * 256 + i];
    __syncthreads();
    float acc = (float)g_cnt[g] * bjk[c];
    for (int k = 0; k < 256; k++) acc += ps[k] * Wjk[k * 64 + c];
    g_pooled[g * 64 + c] = acc;
}

// ---------------- classifier ----------------
__global__ void __launch_bounds__(128) classifier_kernel(
    const float* __restrict__ Wc1, const float* __restrict__ bc1,
    const float* __restrict__ gamma, const float* __restrict__ beta,
    const float* __restrict__ Wc2, const float* __restrict__ bc2,
    float* __restrict__ out)
{
    extern __shared__ float sm[];
    float* W1s = sm;                  // [64][64]
    float* zsm = W1s + 64 * 64;       // [64][129]
    float* scale_s = zsm + 64 * 129;
    float* shift_s = scale_s + 64;

    int tid = threadIdx.x;
    for (int i = tid; i < 64 * 64; i += 128) W1s[i] = Wc1[i];
    __syncthreads();

    float acc[64];
#pragma unroll
    for (int c = 0; c < 64; c++) acc[c] = bc1[c];
    for (int k = 0; k < 64; k++) {
        float pk = g_pooled[tid * 64 + k];
#pragma unroll
        for (int c = 0; c < 64; c++) acc[c] += pk * W1s[k * 64 + c];
    }
#pragma unroll
    for (int c = 0; c < 64; c++) zsm[c * 129 + tid] = acc[c];
    __syncthreads();

    if (tid < 64) {
        int c = tid;
        float s = 0.f;
        for (int g = 0; g < GNUM; g++) s += zsm[c * 129 + g];
        float mu = s / GNUM;
        float v = 0.f;
        for (int g = 0; g < GNUM; g++) {
            float d = zsm[c * 129 + g] - mu;
            v += d * d;
        }
        v /= GNUM;
        float sc = gamma[c] * rsqrtf(v + 1e-5f);
        scale_s[c] = sc;
        shift_s[c] = beta[c] - mu * sc;
    }
    __syncthreads();

    float o[OUT_CH];
#pragma unroll
    for (int j = 0; j < OUT_CH; j++) o[j] = bc2[j];
    for (int c = 0; c < 64; c++) {
        float zn = fmaxf(zsm[c * 129 + tid] * scale_s[c] + shift_s[c], 0.f);
#pragma unroll
        for (int j = 0; j < OUT_CH; j++) o[j] += zn * Wc2[c * OUT_CH + j];
    }
#pragma unroll
    for (int j = 0; j < OUT_CH; j++) out[tid * OUT_CH + j] = o[j];
}

// ---------------- launch ----------------
extern "C" void kernel_launch(void* const* d_in, const int* in_sizes, int n_in,
                              void* d_out, int out_size)
{
    const float* x     = (const float*)d_in[0];
    const int*   ei    = (const int*)d_in[1];
    const int*   batch = (const int*)d_in[2];
    const float* W1f = (const float*)d_in[3];
    const float* b1f = (const float*)d_in[4];
    const float* W2f = (const float*)d_in[5];
    const float* b2f = (const float*)d_in[6];
    const float* W1r = (const float*)d_in[7];
    const float* b1r = (const float*)d_in[8];
    const float* W2r = (const float*)d_in[9];
    const float* b2r = (const float*)d_in[10];
    const float* Wjk = (const float*)d_in[11];
    const float* bjk = (const float*)d_in[12];
    const float* Wc1 = (const float*)d_in[13];
    const float* bc1 = (const float*)d_in[14];
    const float* gm  = (const float*)d_in[15];
    const float* bt  = (const float*)d_in[16];
    const float* Wc2 = (const float*)d_in[17];
    const float* bc2 = (const float*)d_in[18];
    float* out = (float*)d_out;

    void *p_deg, *p_pcat, *p_cnt, *p_y, *p_t;
    cudaGetSymbolAddress(&p_deg, g_deg);
    cudaGetSymbolAddress(&p_pcat, g_pcat);
    cudaGetSymbolAddress(&p_cnt, g_cnt);
    cudaGetSymbolAddress(&p_y, g_y);
    cudaGetSymbolAddress(&p_t, g_t);
    float* y = (float*)p_y;
    float* t = (float*)p_t;

    const size_t SM_Y0  = (128 * 65 + 128 * 64) * sizeof(float);                 // 66048
    const size_t SM_MLP = (64 * 65 * 2 + 4096 * 2) * sizeof(float) + 64 * 4;     // 66304
    const size_t SM_CLS = (64 * 64 + 64 * 129 + 128) * sizeof(float);            // 49920

    cudaFuncSetAttribute(gemm_y0_kernel, cudaFuncAttributeMaxDynamicSharedMemorySize, (int)SM_Y0);
    cudaFuncSetAttribute(mlp2_kernel<true>,  cudaFuncAttributeMaxDynamicSharedMemorySize, (int)SM_MLP);
    cudaFuncSetAttribute(mlp2_kernel<false>, cudaFuncAttributeMaxDynamicSharedMemorySize, (int)SM_MLP);
    cudaFuncSetAttribute(classifier_kernel, cudaFuncAttributeMaxDynamicSharedMemorySize, (int)SM_CLS);

    const int EB = (NE + 255) / 256;       // 6250
    const int SB = (NN + 1023) / 1024;     // 98
    const int GB64 = (NN + 63) / 64;       // 1563

    // zero + CSR build + counts
    cudaMemsetAsync(p_deg, 0, NN * sizeof(int), 0);
    cudaMemsetAsync(p_pcat, 0, GNUM * 256 * sizeof(float), 0);
    cudaMemsetAsync(p_cnt, 0, GNUM * sizeof(int), 0);
    hist_kernel<<<EB, 256>>>(ei);
    scan1_kernel<<<SB, 256>>>();
    scan2_kernel<<<1, 128>>>(SB);
    scan3_kernel<<<SB, 256>>>();
    fill_kernel<<<EB, 256>>>(ei);
    cnt_kernel<<<(NN + 255) / 256, 256>>>(batch);

    // y0 = x @ W1f
    gemm_y0_kernel<<<GB64, 256, SM_Y0>>>(x, W1f);

    // layers
    for (int l = 0; l < 4; l++) {
        const float* b1 = (l == 0) ? b1f : b1r + (size_t)(l - 1) * 64;
        const float* W2 = (l == 0) ? W2f : W2r + (size_t)(l - 1) * 4096;
        const float* b2 = (l == 0) ? b2f : b2r + (size_t)(l - 1) * 64;
        gather_kernel<<<EB, 256>>>(y, b1, t);
        if (l < 3) {
            const float* W1n = W1r + (size_t)l * 4096;
            mlp2_kernel<true><<<GB64, 256, SM_MLP>>>(t, W2, b2, batch, l, W1n, y);
        } else {
            mlp2_kernel<false><<<GB64, 256, SM_MLP>>>(t, W2, b2, batch, l, nullptr, nullptr);
        }
    }

    // JK projection + classifier
    proj_kernel<<<GNUM, 64>>>(Wjk, bjk);
    classifier_kernel<<<1, 128, SM_CLS>>>(Wc1, bc1, gm, bt, Wc2, bc2, out);
}